// round 3
// baseline (speedup 1.0000x reference)
#include <cuda_runtime.h>
#include <cstdint>

// Problem constants (fixed by the reference)
#define B_ 32
#define S_ 512
#define P_ 8
#define K_ 256
#define D_ 64
#define NROWS (B_ * S_ * P_)   // 131072 rows of K=256 logits each

#define FULL 0xffffffffu
#define NEG_INF __int_as_float(0xff800000)

// ---------------------------------------------------------------------------
// JAX threefry2x32, partitionable mode, key = jax.random.key(42) -> (0, 42).
// Per-element 64-bit counter = flat index i (hi word 0). Draw = out0 ^ out1.
// ---------------------------------------------------------------------------
__device__ __forceinline__ uint32_t rotl32(uint32_t x, int r) {
    return __funnelshift_l(x, x, r);
}

__device__ __forceinline__ uint32_t threefry_bits(uint32_t i) {
    const uint32_t ks0 = 0u;
    const uint32_t ks1 = 42u;
    const uint32_t ks2 = 0x1BD11BDAu ^ 0u ^ 42u;
    uint32_t x0 = 0u + ks0;
    uint32_t x1 = i + ks1;
#define TF_ROUND(r) { x0 += x1; x1 = rotl32(x1, (r)) ^ x0; }
    TF_ROUND(13) TF_ROUND(15) TF_ROUND(26) TF_ROUND(6)
    x0 += ks1; x1 += ks2 + 1u;
    TF_ROUND(17) TF_ROUND(29) TF_ROUND(16) TF_ROUND(24)
    x0 += ks2; x1 += ks0 + 2u;
    TF_ROUND(13) TF_ROUND(15) TF_ROUND(26) TF_ROUND(6)
    x0 += ks0; x1 += ks1 + 3u;
    TF_ROUND(17) TF_ROUND(29) TF_ROUND(16) TF_ROUND(24)
    x0 += ks1; x1 += ks2 + 4u;
    TF_ROUND(13) TF_ROUND(15) TF_ROUND(26) TF_ROUND(6)
    x0 += ks2; x1 += ks0 + 5u;
#undef TF_ROUND
    return x0 ^ x1;
}

// jax.random.uniform(minval=tiny) -> gumbel, matching _uniform + _gumbel in fp32
__device__ __forceinline__ float gumbel_from_bits(uint32_t bits) {
    float f = __uint_as_float((bits >> 9) | 0x3f800000u) - 1.0f;  // [0, 1)
    float u = fmaxf(f, 1.17549435e-38f);                          // minval = tiny
    return -logf(-logf(u));
}

// Cold exact path: e_k + gumbel_k, recomputing the hash. __noinline__ keeps the
// hot loop compact (called ~2x per 256-element row).
__device__ __noinline__ float exact_score(const float* __restrict__ erow,
                                          uint32_t row_base, int k) {
    uint32_t bits = threefry_bits(row_base + (uint32_t)k);
    return __ldg(erow + k) + gumbel_from_bits(bits);
}

// ---------------------------------------------------------------------------
// One warp per (b, s, p) row. Screen-then-verify:
//   ub'_k = e_k - (ln2*2^-23) * float(bits(v_k)),  v_k = 1 - u_k (exact)
// satisfies exact_k <= ub'_k + 127*ln2 for all k (g <= -ln v and exponent
// bit-hack underestimates log2(v)). Exact scores (same fp32 path as before)
// are computed only for the top-ub element and the few survivors.
// ---------------------------------------------------------------------------
__global__ void __launch_bounds__(256) symbolic_gumbel_kernel(
    const int*   __restrict__ inputs,       // [B, S] int32
    const float* __restrict__ pattern_map,  // [N_CAT, P, K]
    const float* __restrict__ symbols,      // [K, D]
    float*       __restrict__ out)          // [B, S, P*D]
{
    const int warp = (blockIdx.x * blockDim.x + threadIdx.x) >> 5;
    const int lane = threadIdx.x & 31;

    const int row = warp;                    // grid covers exactly NROWS warps
    const int bs  = row >> 3;
    const int p   = row & 7;
    const int cat = __ldg(&inputs[bs]);

    const float* erow = pattern_map + ((size_t)cat * P_ + p) * K_;
    const uint32_t row_base = (uint32_t)row * (uint32_t)K_;
    const uint32_t base = row_base + (uint32_t)(lane * 8);

    const float4* e4 = reinterpret_cast<const float4*>(erow + lane * 8);
    float4 ea = __ldg(&e4[0]);
    float4 eb = __ldg(&e4[1]);
    float e[8] = {ea.x, ea.y, ea.z, ea.w, eb.x, eb.y, eb.z, eb.w};

    // ---- Pass 1: cheap upper bounds (shifted by -127*ln2) ----
    const float C2 = 8.2629582e-8f;   // ln2 * 2^-23
    float ub[8];
    float best_ub  = NEG_INF;
    int   best_idx = 0;
#pragma unroll
    for (int j = 0; j < 8; j++) {
        uint32_t bits = threefry_bits(base + (uint32_t)j);
        float w  = __uint_as_float((bits >> 9) | 0x3f800000u);  // 1+u in [1,2)
        float v  = 2.0f - w;                                    // 1-u in (0,1], exact
        float vf = (float)__float_as_int(v);
        float s  = fmaf(vf, -C2, e[j]);                         // ub'_j
        ub[j] = s;
        if (s > best_ub) { best_ub = s; best_idx = lane * 8 + j; }
    }

    // Warp argmax of ub (any top element works; lower index for determinism)
#pragma unroll
    for (int off = 16; off > 0; off >>= 1) {
        float ob = __shfl_xor_sync(FULL, best_ub, off);
        int   oi = __shfl_xor_sync(FULL, best_idx, off);
        if (ob > best_ub || (ob == best_ub && oi < best_idx)) {
            best_ub = ob; best_idx = oi;
        }
    }

    // ---- Lower bound: exact score of the top-ub element ----
    const int owner = best_idx >> 3;  // lane owning best_idx
    float lbx = 0.0f;
    if (lane == owner) lbx = exact_score(erow, row_base, best_idx);
    const float LB = __shfl_sync(FULL, lbx, owner);
    // candidates: ub'_j >= LB - 127*ln2 - slack  (slack covers ub fp32 rounding)
    const float thresh = LB - 88.029691931f - 1e-3f;

    // ---- Pass 2: exact scores for survivors only ----
    float bestx = NEG_INF;
    int   bestk = K_;
#pragma unroll
    for (int j = 0; j < 8; j++) {
        bool cand = (ub[j] >= thresh);
        if (__any_sync(FULL, cand)) {
            int   k = lane * 8 + j;
            float x = NEG_INF;
            if (cand) x = exact_score(erow, row_base, k);
            if (x > bestx || (x == bestx && k < bestk)) { bestx = x; bestk = k; }
        }
    }

    // Warp argmax with first-index tie-break (matches jnp.argmax)
#pragma unroll
    for (int off = 16; off > 0; off >>= 1) {
        float ob = __shfl_xor_sync(FULL, bestx, off);
        int   ok = __shfl_xor_sync(FULL, bestk, off);
        if (ob > bestx || (ob == bestx && ok < bestk)) { bestx = ob; bestk = ok; }
    }

    // Copy symbols[bestk, :] (64 floats = 256B) to out[row, :], 2 floats/lane
    const float2* srow = reinterpret_cast<const float2*>(symbols + (size_t)bestk * D_);
    float2 val = __ldg(&srow[lane]);
    float2* orow = reinterpret_cast<float2*>(out + (size_t)row * D_);
    orow[lane] = val;
}

extern "C" void kernel_launch(void* const* d_in, const int* in_sizes, int n_in,
                              void* d_out, int out_size) {
    const int*   inputs      = (const int*)  d_in[0];  // [32, 512] int32
    const float* pattern_map = (const float*)d_in[1];  // [50000, 8, 256]
    const float* symbols     = (const float*)d_in[2];  // [256, 64]
    // d_in[3] = tau (== 1.0, positive): argmax invariant; straight-through
    // weights are one-hot to fp32 rounding, so tau is unused.
    float* out = (float*)d_out;                        // [32, 512, 512]

    const int threads = 256;                 // 8 warps -> 8 rows per block
    const int blocks  = NROWS / 8;           // 16384
    symbolic_gumbel_kernel<<<blocks, threads>>>(inputs, pattern_map, symbols, out);
}

// round 4
// speedup vs baseline: 1.0674x; 1.0674x over previous
#include <cuda_runtime.h>
#include <cstdint>

// Problem constants (fixed by the reference)
#define B_ 32
#define S_ 512
#define P_ 8
#define K_ 256
#define D_ 64
#define NROWS (B_ * S_ * P_)   // 131072 rows of K=256 logits each

#define FULL 0xffffffffu
#define NEG_INF __int_as_float(0xff800000)

// ---------------------------------------------------------------------------
// JAX threefry2x32, partitionable mode, key = jax.random.key(42) -> (0, 42).
// Per-element 64-bit counter = flat index i (hi word 0). Draw = out0 ^ out1.
// ---------------------------------------------------------------------------
__device__ __forceinline__ uint32_t rotl32(uint32_t x, int r) {
    return __funnelshift_l(x, x, r);
}

__device__ __forceinline__ uint32_t threefry_bits(uint32_t i) {
    const uint32_t ks0 = 0u;
    const uint32_t ks1 = 42u;
    const uint32_t ks2 = 0x1BD11BDAu ^ 0u ^ 42u;
    uint32_t x0 = 0u + ks0;
    uint32_t x1 = i + ks1;
#define TF_ROUND(r) { x0 += x1; x1 = rotl32(x1, (r)) ^ x0; }
    TF_ROUND(13) TF_ROUND(15) TF_ROUND(26) TF_ROUND(6)
    x0 += ks1; x1 += ks2 + 1u;
    TF_ROUND(17) TF_ROUND(29) TF_ROUND(16) TF_ROUND(24)
    x0 += ks2; x1 += ks0 + 2u;
    TF_ROUND(13) TF_ROUND(15) TF_ROUND(26) TF_ROUND(6)
    x0 += ks0; x1 += ks1 + 3u;
    TF_ROUND(17) TF_ROUND(29) TF_ROUND(16) TF_ROUND(24)
    x0 += ks1; x1 += ks2 + 4u;
    TF_ROUND(13) TF_ROUND(15) TF_ROUND(26) TF_ROUND(6)
    x0 += ks2; x1 += ks0 + 5u;
#undef TF_ROUND
    return x0 ^ x1;
}

// Exact path, bit-identical to the reference fp32 computation. INLINE (no CALL).
__device__ __forceinline__ float exact_score(const float* __restrict__ erow,
                                             uint32_t row_base, int k) {
    uint32_t bits = threefry_bits(row_base + (uint32_t)k);
    float f = __uint_as_float((bits >> 9) | 0x3f800000u) - 1.0f;  // u in [0,1)
    float u = fmaxf(f, 1.17549435e-38f);
    float g = -logf(-logf(u));
    return __ldg(erow + k) + g;   // e reloaded from L1 (hot)
}

// ---------------------------------------------------------------------------
// One warp per (b, s, p) row. Screen-then-verify:
//   s_j = e_j - C2*float(bits(v_j)),  v_j = 1 - u_j  (exact in fp32)
//   exact_j <= s_j + 127*ln2 + eps   (g <= -ln v, exponent-bit-hack lower-
//                                     bounds log2 v; eps covers fp rounding)
// Exact scores are computed only for the top-s element (-> LB) and the few
// elements whose bound clears LB. All true argmax candidates provably survive.
// ---------------------------------------------------------------------------
__global__ void __launch_bounds__(256) symbolic_gumbel_kernel(
    const int*   __restrict__ inputs,       // [B, S] int32
    const float* __restrict__ pattern_map,  // [N_CAT, P, K]
    const float* __restrict__ symbols,      // [K, D]
    float*       __restrict__ out)          // [B, S, P*D]
{
    const int warp = (blockIdx.x * blockDim.x + threadIdx.x) >> 5;
    const int lane = threadIdx.x & 31;

    const int row = warp;                    // grid covers exactly NROWS warps
    const int bs  = row >> 3;
    const int p   = row & 7;
    const int cat = __ldg(&inputs[bs]);

    const float* erow = pattern_map + ((size_t)cat * P_ + p) * K_;
    const uint32_t row_base = (uint32_t)row * (uint32_t)K_;
    const uint32_t base = row_base + (uint32_t)(lane * 8);

    const float4* e4 = reinterpret_cast<const float4*>(erow + lane * 8);
    float4 ea = __ldg(&e4[0]);
    float4 eb = __ldg(&e4[1]);
    float e[8] = {ea.x, ea.y, ea.z, ea.w, eb.x, eb.y, eb.z, eb.w};

    // ---- Pass 1: cheap bounds (shifted by -127*ln2), lane max only ----
    const float C2 = 8.2629582e-8f;   // ln2 * 2^-23
    float s[8];
    float smax = NEG_INF;
#pragma unroll
    for (int j = 0; j < 8; j++) {
        uint32_t bits = threefry_bits(base + (uint32_t)j);
        float w  = __uint_as_float((bits >> 9) | 0x3f800000u);  // 1+u in [1,2)
        float v  = 2.0f - w;                                    // 1-u, exact
        float vf = (float)__float_as_int(v);
        float sj = fmaf(vf, -C2, e[j]);
        s[j] = sj;
        smax = fmaxf(smax, sj);                                 // FMNMX, no index
    }

    // Warp max of the bound (value only)
#pragma unroll
    for (int off = 16; off > 0; off >>= 1)
        smax = fmaxf(smax, __shfl_xor_sync(FULL, smax, off));

    // Post-hoc owner: lowest j in this lane matching smax (if any)
    int jm = 8;
#pragma unroll
    for (int j = 7; j >= 0; j--)
        if (s[j] == smax) jm = j;
    unsigned ball = __ballot_sync(FULL, jm < 8);
    int owner = __ffs(ball) - 1;

    // ---- LB: exact score of the top-bound element (inline, one lane) ----
    int   k_top_l = lane * 8 + jm;
    float exl = 0.0f;
    if (lane == owner) exl = exact_score(erow, row_base, k_top_l);
    const float LB    = __shfl_sync(FULL, exl, owner);
    const int   k_top = __shfl_sync(FULL, k_top_l, owner);

    // candidates: s_j >= LB - 127*ln2 - slack
    const float thresh = LB - 88.029691931f - 1e-3f;

    // ---- Pass 2: exact scores for survivors only (~2 per row) ----
    float bestx = LB;
    int   bestk = k_top;
#pragma unroll
    for (int j = 0; j < 8; j++) {
        bool cand = (s[j] >= thresh);
        if (__any_sync(FULL, cand)) {
            int   k = lane * 8 + j;
            float x = NEG_INF;
            if (cand) x = exact_score(erow, row_base, k);
            if (x > bestx || (x == bestx && k < bestk)) { bestx = x; bestk = k; }
        }
    }

    // Warp argmax with first-index tie-break (matches jnp.argmax)
#pragma unroll
    for (int off = 16; off > 0; off >>= 1) {
        float ob = __shfl_xor_sync(FULL, bestx, off);
        int   ok = __shfl_xor_sync(FULL, bestk, off);
        if (ob > bestx || (ob == bestx && ok < bestk)) { bestx = ob; bestk = ok; }
    }

    // Copy symbols[bestk, :] (64 floats = 256B) to out[row, :], 2 floats/lane
    const float2* srow = reinterpret_cast<const float2*>(symbols + (size_t)bestk * D_);
    float2 val = __ldg(&srow[lane]);
    float2* orow = reinterpret_cast<float2*>(out + (size_t)row * D_);
    orow[lane] = val;
}

extern "C" void kernel_launch(void* const* d_in, const int* in_sizes, int n_in,
                              void* d_out, int out_size) {
    const int*   inputs      = (const int*)  d_in[0];  // [32, 512] int32
    const float* pattern_map = (const float*)d_in[1];  // [50000, 8, 256]
    const float* symbols     = (const float*)d_in[2];  // [256, 64]
    // d_in[3] = tau (== 1.0, positive): argmax invariant; straight-through
    // weights are one-hot to fp32 rounding, so tau is unused.
    float* out = (float*)d_out;                        // [32, 512, 512]

    const int threads = 256;                 // 8 warps -> 8 rows per block
    const int blocks  = NROWS / 8;           // 16384
    symbolic_gumbel_kernel<<<blocks, threads>>>(inputs, pattern_map, symbols, out);
}